// round 1
// baseline (speedup 1.0000x reference)
#include <cuda_runtime.h>
#include <cuda_bf16.h>

// Skipgram negative-sampling loss.
// Inputs (metadata order):
//   d_in[0] input_idx  int32  [N]
//   d_in[1] output_idx int32  [N]
//   d_in[2] neg_idx    int32  [N, K]
//   d_in[3] W_in       fp32   [N_WORDS, D]
//   d_in[4] W_out      fp32   [N_WORDS, D]
// Output: scalar fp32 loss.

#define N_SAMPLES 65536
#define DIMS      128
#define KNEG      10
#define WARPS_PER_BLOCK 8

__device__ double g_acc;

__global__ void sg_zero_kernel() {
    g_acc = 0.0;
}

__device__ __forceinline__ float warp_sum(float v) {
#pragma unroll
    for (int o = 16; o > 0; o >>= 1)
        v += __shfl_xor_sync(0xffffffff, v, o);
    return v;
}

// numerically stable log(sigmoid(x)) = min(x,0) - log1p(exp(-|x|))
__device__ __forceinline__ float logsig(float x) {
    return fminf(x, 0.0f) - log1pf(__expf(-fabsf(x)));
}

__global__ __launch_bounds__(WARPS_PER_BLOCK * 32)
void sg_compute_kernel(const int* __restrict__ input_idx,
                       const int* __restrict__ output_idx,
                       const int* __restrict__ neg_idx,
                       const float* __restrict__ W_in,
                       const float* __restrict__ W_out) {
    const int warp = threadIdx.x >> 5;
    const int lane = threadIdx.x & 31;
    const int n = blockIdx.x * WARPS_PER_BLOCK + warp;

    // Gather the 12 rows this sample needs. Each lane reads one float4 of
    // each 128-float row -> fully coalesced 512B warp reads.
    const float4* a4 = reinterpret_cast<const float4*>(
        W_in + (size_t)input_idx[n] * DIMS);
    float4 a = __ldg(a4 + lane);

    // Batch all 11 operand loads before any reduction to maximize MLP.
    float4 b[KNEG + 1];
    {
        const float4* p = reinterpret_cast<const float4*>(
            W_out + (size_t)output_idx[n] * DIMS);
        b[0] = __ldg(p + lane);
    }
#pragma unroll
    for (int k = 0; k < KNEG; k++) {
        const float4* p = reinterpret_cast<const float4*>(
            W_out + (size_t)neg_idx[n * KNEG + k] * DIMS);
        b[k + 1] = __ldg(p + lane);
    }

    // Per-lane partial dots
    float part[KNEG + 1];
#pragma unroll
    for (int j = 0; j < KNEG + 1; j++) {
        part[j] = a.x * b[j].x + a.y * b[j].y + a.z * b[j].z + a.w * b[j].w;
    }

    // Warp reductions + log-sigmoid
    float local = 0.0f;
#pragma unroll
    for (int j = 0; j < KNEG + 1; j++) {
        float d = warp_sum(part[j]);
        if (lane == 0) {
            // j==0 is the positive sample: logsig(d); negatives: logsig(-d)
            local += logsig(j == 0 ? d : -d);
        }
    }

    // Block reduce -> one double atomic per block
    __shared__ float s[WARPS_PER_BLOCK];
    if (lane == 0) s[warp] = local;
    __syncthreads();
    if (threadIdx.x == 0) {
        float t = 0.0f;
#pragma unroll
        for (int i = 0; i < WARPS_PER_BLOCK; i++) t += s[i];
        atomicAdd(&g_acc, (double)t);
    }
}

__global__ void sg_finalize_kernel(float* __restrict__ out) {
    out[0] = (float)(g_acc / (double)N_SAMPLES);
}

extern "C" void kernel_launch(void* const* d_in, const int* in_sizes, int n_in,
                              void* d_out, int out_size) {
    const int*   input_idx  = (const int*)d_in[0];
    const int*   output_idx = (const int*)d_in[1];
    const int*   neg_idx    = (const int*)d_in[2];
    const float* W_in       = (const float*)d_in[3];
    const float* W_out      = (const float*)d_in[4];
    float* out = (float*)d_out;

    sg_zero_kernel<<<1, 1>>>();
    const int blocks = N_SAMPLES / WARPS_PER_BLOCK;  // 8192
    sg_compute_kernel<<<blocks, WARPS_PER_BLOCK * 32>>>(
        input_idx, output_idx, neg_idx, W_in, W_out);
    sg_finalize_kernel<<<1, 1>>>(out);
}